// round 15
// baseline (speedup 1.0000x reference)
#include <cuda_runtime.h>
#include <cuda_fp16.h>

#define BB 4
#define CC 192
#define HWP 4096
#define KIMP 1728
#define LEAK 0.01f
typedef long long ll;
typedef unsigned int u32;

// ---------------- device scratch (BASE SYMBOLS ONLY) ----------------
__device__ __align__(128) __half g_x1h[(size_t)BB * HWP * CC], g_x1l[(size_t)BB * HWP * CC];
__device__ __align__(128) __half g_x2h[(size_t)BB * HWP * CC], g_x2l[(size_t)BB * HWP * CC];
__device__ __align__(128) __half g_th [(size_t)BB * HWP * CC], g_tl [(size_t)BB * HWP * CC];
__device__ __align__(128) __half g_f1h[(size_t)BB * HWP * CC], g_f1l[(size_t)BB * HWP * CC];
__device__ __align__(128) __half g_f2h[(size_t)BB * HWP * CC], g_f2l[(size_t)BB * HWP * CC];
__device__ __align__(128) __half g_wallh[(size_t)4 * CC * KIMP];
__device__ __align__(128) __half g_walll[(size_t)4 * CC * KIMP];
__device__ __align__(128) __half g_rfh[(size_t)BB * CC * HWP], g_rfl[(size_t)BB * CC * HWP];
__device__ __align__(128) __half g_o1h[(size_t)BB * CC * 1024], g_o1l[(size_t)BB * CC * 1024];
__device__ __align__(128) __half g_o2h[(size_t)BB * CC * 256],  g_o2l[(size_t)BB * CC * 256];
__device__ __align__(128) float  g_corr[(size_t)BB * HWP * HWP];
__device__ __align__(128) __half g_ch[(size_t)BB * HWP * HWP], g_cl[(size_t)BB * HWP * HWP];
__device__ __align__(128) __half g_c1h[(size_t)BB * 1024 * 1024], g_c1l[(size_t)BB * 1024 * 1024];
__device__ __align__(128) __half g_c2h[(size_t)BB * 256 * 256],  g_c2l[(size_t)BB * 256 * 256];

// ---------------- helpers ----------------
__device__ __forceinline__ u32 su32(const void* p) {
    u32 a;
    asm("{ .reg .u64 t; cvta.to.shared.u64 t, %1; cvt.u32.u64 %0, t; }" : "=r"(a) : "l"(p));
    return a;
}
__device__ __forceinline__ void h16(float v, __half& h, __half& l) {
    h = __float2half(v);
    l = __float2half(v - __half2float(h));
}
__device__ __forceinline__ void ldsm4(u32 addr, u32& r0, u32& r1, u32& r2, u32& r3) {
    asm volatile("ldmatrix.sync.aligned.m8n8.x4.shared.b16 {%0,%1,%2,%3}, [%4];"
        : "=r"(r0), "=r"(r1), "=r"(r2), "=r"(r3) : "r"(addr));
}
__device__ __forceinline__ void mma16816(float* c, u32 a0, u32 a1, u32 a2, u32 a3,
                                         u32 b0, u32 b1) {
    asm volatile("mma.sync.aligned.m16n8k16.row.col.f32.f16.f16.f32 "
        "{%0,%1,%2,%3}, {%4,%5,%6,%7}, {%8,%9}, {%0,%1,%2,%3};"
        : "+f"(c[0]), "+f"(c[1]), "+f"(c[2]), "+f"(c[3])
        : "r"(a0), "r"(a1), "r"(a2), "r"(a3), "r"(b0), "r"(b1));
}

// One k16 step of a 32x32 warp tile, 3-term split. Tiles [rows][40] halves.
__device__ __forceinline__ void mma_step(u32 aH, u32 aL, u32 bH, u32 bL,
                                         int mOff, int nOff, int kOff, int lane,
                                         float c[2][4][4]) {
    u32 ah[2][4], al[2][4];
    const int ar = lane & 15, ac = (lane >> 4) << 3;
#pragma unroll
    for (int mi = 0; mi < 2; mi++) {
        u32 off = (u32)(((mOff + mi * 16 + ar) * 40 + kOff + ac) * 2);
        ldsm4(aH + off, ah[mi][0], ah[mi][1], ah[mi][2], ah[mi][3]);
        ldsm4(aL + off, al[mi][0], al[mi][1], al[mi][2], al[mi][3]);
    }
    u32 bh[8], bl[8];
    const int g = lane >> 3;
    const int bn = ((g >> 1) << 3) + (lane & 7);
    const int bk = (g & 1) << 3;
#pragma unroll
    for (int hf = 0; hf < 2; hf++) {
        u32 off = (u32)(((nOff + hf * 16 + bn) * 40 + kOff + bk) * 2);
        ldsm4(bH + off, bh[hf*4+0], bh[hf*4+1], bh[hf*4+2], bh[hf*4+3]);
        ldsm4(bL + off, bl[hf*4+0], bl[hf*4+1], bl[hf*4+2], bl[hf*4+3]);
    }
#pragma unroll
    for (int mi = 0; mi < 2; mi++)
#pragma unroll
        for (int j = 0; j < 4; j++) {
            mma16816(c[mi][j], ah[mi][0], ah[mi][1], ah[mi][2], ah[mi][3], bh[j*2], bh[j*2+1]);
            mma16816(c[mi][j], ah[mi][0], ah[mi][1], ah[mi][2], ah[mi][3], bl[j*2], bl[j*2+1]);
            mma16816(c[mi][j], al[mi][0], al[mi][1], al[mi][2], al[mi][3], bh[j*2], bh[j*2+1]);
        }
}

__device__ __forceinline__ void frags_to_T(float* T, int TLD, int mW, int nW, int lane,
                                           float c[2][4][4]) {
    const int tq = lane >> 2, tc = (lane & 3) * 2;
#pragma unroll
    for (int mi = 0; mi < 2; mi++)
#pragma unroll
        for (int j = 0; j < 4; j++) {
            int rr = mW + mi * 16 + tq;
            int cc = nW + j * 8 + tc;
            T[rr * TLD + cc]     = c[mi][j][0];
            T[rr * TLD + cc + 1] = c[mi][j][1];
            T[(rr + 8) * TLD + cc]     = c[mi][j][2];
            T[(rr + 8) * TLD + cc + 1] = c[mi][j][3];
        }
}

// ---------------- prep ----------------
__global__ void tsplit_k(const float* __restrict__ in, __half* __restrict__ oh,
                         __half* __restrict__ ol) {
    __shared__ float t[32][33];
    const int b = blockIdx.z, x0 = blockIdx.x << 5, y0 = blockIdx.y << 5;
    const int tx = threadIdx.x, ty = threadIdx.y;
    const float* ib = in + (ll)b * CC * HWP;
#pragma unroll
    for (int i = 0; i < 32; i += 8)
        t[ty + i][tx] = ib[(ll)(y0 + ty + i) * HWP + x0 + tx];
    __syncthreads();
    const ll ob = (ll)b * HWP * CC;
#pragma unroll
    for (int i = 0; i < 32; i += 8) {
        __half h, l; h16(t[tx][ty + i], h, l);
        ll o = ob + (ll)(x0 + ty + i) * CC + y0 + tx;
        oh[o] = h; ol[o] = l;
    }
}
// all 4 weight sets in ONE launch: grid.y selects set
__global__ __launch_bounds__(256)
void wsplit4_k(const float* __restrict__ w0, const float* __restrict__ w1,
               const float* __restrict__ w2, const float* __restrict__ w3,
               __half* __restrict__ oh, __half* __restrict__ ol) {
    int t = blockIdx.x * 256 + threadIdx.x;
    if (t >= CC * KIMP) return;
    const int s = blockIdx.y;
    const float* w = (s == 0) ? w0 : (s == 1) ? w1 : (s == 2) ? w2 : w3;
    int co = t / KIMP, rem = t % KIMP, kp = rem / CC, ci = rem % CC;
    __half h, l; h16(w[((ll)co * CC + ci) * 9 + kp], h, l);
    size_t off = (size_t)s * CC * KIMP;
    oh[off + t] = h; ol[off + t] = l;
}
// elementwise split fp32 -> pair planes
__global__ __launch_bounds__(256)
void psplit_k(const float* __restrict__ x, __half* __restrict__ oh,
              __half* __restrict__ ol, int n) {
    int i = (blockIdx.x * 256 + threadIdx.x) * 4;
    if (i >= n) return;
    float4 v = *reinterpret_cast<const float4*>(x + i);
    __half h0, l0, h1, l1, h2, l2, h3, l3;
    h16(v.x, h0, l0); h16(v.y, h1, l1); h16(v.z, h2, l2); h16(v.w, h3, l3);
    *reinterpret_cast<__half2*>(oh + i)     = __halves2half2(h0, h1);
    *reinterpret_cast<__half2*>(oh + i + 2) = __halves2half2(h2, h3);
    *reinterpret_cast<__half2*>(ol + i)     = __halves2half2(l0, l1);
    *reinterpret_cast<__half2*>(ol + i + 2) = __halves2half2(l2, l3);
}

// ===========================================================================
// gc: conv GEMM (implicit im2col), unchanged from R14 (proven).
// ===========================================================================
template<int MODE>
__global__ __launch_bounds__(256, 2)
void gc(const __half* __restrict__ Awh, const __half* __restrict__ Awl,
        const __half* __restrict__ Xh_, const __half* __restrict__ Xl_, ll xbat,
        const float* __restrict__ bias, const float* __restrict__ resid, ll rbat,
        __half* __restrict__ OH, __half* __restrict__ OL, ll obat)
{
    constexpr int AEL = 64 * 40, BEL = 128 * 40;
    constexpr int STEL = 2 * (AEL + BEL);
    constexpr int TLD = 132;

    extern __shared__ float sm[];
    __half* smh = reinterpret_cast<__half*>(sm);
    const u32 sb = su32(smh);
    const int tid = threadIdx.x, w = tid >> 5, lane = tid & 31;
    const int mW = (w & 1) * 32, nW = (w >> 1) * 32;
    const int n0 = blockIdx.x * 128, m0 = blockIdx.y * 64, b = blockIdx.z;

    const __half* Xh = Xh_ + (ll)b * xbat;
    const __half* Xl = Xl_ + (ll)b * xbat;
    const int NC = KIMP / 32;

    uint4 rah, ral, rbh[2], rbl[2];
    auto fetch = [&](int c) {
        {   int r = tid >> 2, u = tid & 3;
            ll a = (ll)(m0 + r) * KIMP + c * 32 + u * 8;
            rah = *reinterpret_cast<const uint4*>(Awh + a);
            ral = *reinterpret_cast<const uint4*>(Awl + a);
        }
        const int kp = c / 6, ci0 = (c % 6) << 5;
        const int kh = kp / 3 - 1, kw = kp % 3 - 1;
#pragma unroll
        for (int i = 0; i < 2; i++) {
            int it = tid + i * 256;
            int r = it >> 2, u = it & 3;
            int p = n0 + r;
            int pr = (p >> 6) + kh, pc = (p & 63) + kw;
            uint4 vh = make_uint4(0,0,0,0), vl = vh;
            if (pr >= 0 && pr < 64 && pc >= 0 && pc < 64) {
                ll a = (ll)((pr << 6) + pc) * CC + ci0 + u * 8;
                vh = *reinterpret_cast<const uint4*>(Xh + a);
                vl = *reinterpret_cast<const uint4*>(Xl + a);
            }
            rbh[i] = vh; rbl[i] = vl;
        }
    };
    auto stash = [&](int s) {
        __half* A_h = smh + s * STEL;  __half* A_l = A_h + AEL;
        __half* B_h = A_l + AEL;       __half* B_l = B_h + BEL;
        {   int r = tid >> 2, u = tid & 3;
            int o = r * 40 + u * 8;
            *reinterpret_cast<uint4*>(A_h + o) = rah;
            *reinterpret_cast<uint4*>(A_l + o) = ral;
        }
#pragma unroll
        for (int i = 0; i < 2; i++) {
            int it = tid + i * 256;
            int r = it >> 2, u = it & 3;
            int o = r * 40 + u * 8;
            *reinterpret_cast<uint4*>(B_h + o) = rbh[i];
            *reinterpret_cast<uint4*>(B_l + o) = rbl[i];
        }
    };

    float acc[2][4][4];
#pragma unroll
    for (int mi = 0; mi < 2; mi++)
#pragma unroll
        for (int j = 0; j < 4; j++)
#pragma unroll
            for (int e = 0; e < 4; e++) acc[mi][j][e] = 0.f;

    fetch(0); stash(0); __syncthreads();
    for (int c = 0; c < NC; c++) {
        const bool more = (c + 1 < NC);
        if (more) fetch(c + 1);
        const u32 st = sb + (u32)((c & 1) * STEL * 2);
        const u32 aH = st, aL = st + AEL * 2, bH = aL + AEL * 2, bL = bH + BEL * 2;
        mma_step(aH, aL, bH, bL, mW, nW, 0,  lane, acc);
        mma_step(aH, aL, bH, bL, mW, nW, 16, lane, acc);
        if (more) stash((c + 1) & 1);
        __syncthreads();
    }

    float* T = sm;
    frags_to_T(T, TLD, mW, nW, lane, acc);
    __syncthreads();

    for (int idx = tid; idx < 64 * 128; idx += 256) {
        int pi = idx >> 6, coi = idx & 63;
        float v = T[coi * TLD + pi] + bias[m0 + coi];
        v = v > 0.f ? v : LEAK * v;
        if (MODE == 2)
            v += resid[(ll)b * rbat + (ll)(m0 + coi) * HWP + n0 + pi];
        __half h, l; h16(v, h, l);
        ll o = (ll)b * obat + (ll)(n0 + pi) * CC + m0 + coi;
        OH[o] = h; OL[o] = l;
    }
}

// ===========================================================================
// gx: corr GEMM, unchanged from R14 (proven).
// ===========================================================================
__global__ __launch_bounds__(256, 2)
void gx(const __half* __restrict__ Ah_, const __half* __restrict__ Al_,
        const __half* __restrict__ Bh_, const __half* __restrict__ Bl_,
        float* __restrict__ C)
{
    constexpr int AEL = 64 * 40, BEL = 128 * 40;
    constexpr int STEL = 2 * (AEL + BEL);
    constexpr int TLD = 132;

    extern __shared__ float sm[];
    __half* smh = reinterpret_cast<__half*>(sm);
    const u32 sb = su32(smh);
    const int tid = threadIdx.x, w = tid >> 5, lane = tid & 31;
    const int mW = (w & 1) * 32, nW = (w >> 1) * 32;
    const int n0 = blockIdx.x * 128, m0 = blockIdx.y * 64, b = blockIdx.z;

    const __half* Ah = Ah_ + (ll)b * (HWP * CC);
    const __half* Al = Al_ + (ll)b * (HWP * CC);
    const __half* Bh = Bh_ + (ll)b * (HWP * CC);
    const __half* Bl = Bl_ + (ll)b * (HWP * CC);

    uint4 rah, ral, rbh[2], rbl[2];
    auto fetch = [&](int c) {
        {   int r = tid >> 2, u = tid & 3;
            ll a = (ll)(m0 + r) * CC + c * 32 + u * 8;
            rah = *reinterpret_cast<const uint4*>(Ah + a);
            ral = *reinterpret_cast<const uint4*>(Al + a);
        }
#pragma unroll
        for (int i = 0; i < 2; i++) {
            int it = tid + i * 256;
            int r = it >> 2, u = it & 3;
            ll a = (ll)(n0 + r) * CC + c * 32 + u * 8;
            rbh[i] = *reinterpret_cast<const uint4*>(Bh + a);
            rbl[i] = *reinterpret_cast<const uint4*>(Bl + a);
        }
    };
    auto stash = [&](int s) {
        __half* A_h = smh + s * STEL;  __half* A_l = A_h + AEL;
        __half* B_h = A_l + AEL;       __half* B_l = B_h + BEL;
        {   int r = tid >> 2, u = tid & 3;
            int o = r * 40 + u * 8;
            *reinterpret_cast<uint4*>(A_h + o) = rah;
            *reinterpret_cast<uint4*>(A_l + o) = ral;
        }
#pragma unroll
        for (int i = 0; i < 2; i++) {
            int it = tid + i * 256;
            int r = it >> 2, u = it & 3;
            int o = r * 40 + u * 8;
            *reinterpret_cast<uint4*>(B_h + o) = rbh[i];
            *reinterpret_cast<uint4*>(B_l + o) = rbl[i];
        }
    };

    float acc[2][4][4];
#pragma unroll
    for (int mi = 0; mi < 2; mi++)
#pragma unroll
        for (int j = 0; j < 4; j++)
#pragma unroll
            for (int e = 0; e < 4; e++) acc[mi][j][e] = 0.f;

    fetch(0); stash(0); __syncthreads();
    for (int c = 0; c < 6; c++) {
        const bool more = (c + 1 < 6);
        if (more) fetch(c + 1);
        const u32 st = sb + (u32)((c & 1) * STEL * 2);
        const u32 aH = st, aL = st + AEL * 2, bH = aL + AEL * 2, bL = bH + BEL * 2;
        mma_step(aH, aL, bH, bL, mW, nW, 0,  lane, acc);
        mma_step(aH, aL, bH, bL, mW, nW, 16, lane, acc);
        if (more) stash((c + 1) & 1);
        __syncthreads();
    }

    float* T = sm;
    frags_to_T(T, TLD, mW, nW, lane, acc);
    __syncthreads();

    float* Cb = C + (ll)b * ((ll)HWP * HWP);
    for (int idx = tid; idx < 64 * 32; idx += 256) {
        int row = idx >> 5, q4 = idx & 31;
        float4 v = make_float4(T[row * TLD + q4 * 4], T[row * TLD + q4 * 4 + 1],
                               T[row * TLD + q4 * 4 + 2], T[row * TLD + q4 * 4 + 3]);
        *reinterpret_cast<float4*>(Cb + (ll)(m0 + row) * HWP + n0 + q4 * 4) = v;
    }
}

// ===========================================================================
// ga: PURE-LOAD attention GEMM. C[n][m] = sum_k A(m,k)*B(n,k), transposed store.
//  A: corr pair planes [M][K] (lda). B: ref pair planes [N][K] (ldb).
//  TM=128, TN=64, KC=32.
// ===========================================================================
__global__ __launch_bounds__(256, 2)
void ga(const __half* __restrict__ Ah_, const __half* __restrict__ Al_, ll abat, int lda,
        const __half* __restrict__ Bh_, const __half* __restrict__ Bl_, ll bbat, int ldb,
        int K, float* __restrict__ C, ll cbat, int ldc)
{
    constexpr int AEL = 128 * 40, BEL = 64 * 40;
    constexpr int STEL = 2 * (AEL + BEL);
    constexpr int TLD = 68;

    extern __shared__ float sm[];
    __half* smh = reinterpret_cast<__half*>(sm);
    const u32 sb = su32(smh);
    const int tid = threadIdx.x, w = tid >> 5, lane = tid & 31;
    const int mW = (w & 3) * 32, nW = (w >> 2) * 32;
    const int n0 = blockIdx.x * 64, m0 = blockIdx.y * 128, b = blockIdx.z;

    const __half* Ah = Ah_ + (ll)b * abat;
    const __half* Al = Al_ + (ll)b * abat;
    const __half* Bh = Bh_ + (ll)b * bbat;
    const __half* Bl = Bl_ + (ll)b * bbat;
    const int NC = K >> 5;

    uint4 rah[2], ral[2], rbh, rbl;
    auto fetch = [&](int c) {
#pragma unroll
        for (int i = 0; i < 2; i++) {
            int it = tid + i * 256;
            int r = it >> 2, u = it & 3;
            ll a = (ll)(m0 + r) * lda + c * 32 + u * 8;
            rah[i] = *reinterpret_cast<const uint4*>(Ah + a);
            ral[i] = *reinterpret_cast<const uint4*>(Al + a);
        }
        {   int r = tid >> 2, u = tid & 3;
            ll a = (ll)(n0 + r) * ldb + c * 32 + u * 8;
            rbh = *reinterpret_cast<const uint4*>(Bh + a);
            rbl = *reinterpret_cast<const uint4*>(Bl + a);
        }
    };
    auto stash = [&](int s) {
        __half* A_h = smh + s * STEL;  __half* A_l = A_h + AEL;
        __half* B_h = A_l + AEL;       __half* B_l = B_h + BEL;
#pragma unroll
        for (int i = 0; i < 2; i++) {
            int it = tid + i * 256;
            int r = it >> 2, u = it & 3;
            int o = r * 40 + u * 8;
            *reinterpret_cast<uint4*>(A_h + o) = rah[i];
            *reinterpret_cast<uint4*>(A_l + o) = ral[i];
        }
        {   int r = tid >> 2, u = tid & 3;
            int o = r * 40 + u * 8;
            *reinterpret_cast<uint4*>(B_h + o) = rbh;
            *reinterpret_cast<uint4*>(B_l + o) = rbl;
        }
    };

    float acc[2][4][4];
#pragma unroll
    for (int mi = 0; mi < 2; mi++)
#pragma unroll
        for (int j = 0; j < 4; j++)
#pragma unroll
            for (int e = 0; e < 4; e++) acc[mi][j][e] = 0.f;

    fetch(0); stash(0); __syncthreads();
    for (int c = 0; c < NC; c++) {
        const bool more = (c + 1 < NC);
        if (more) fetch(c + 1);
        const u32 st = sb + (u32)((c & 1) * STEL * 2);
        const u32 aH = st, aL = st + AEL * 2, bH = aL + AEL * 2, bL = bH + BEL * 2;
        mma_step(aH, aL, bH, bL, mW, nW, 0,  lane, acc);
        mma_step(aH, aL, bH, bL, mW, nW, 16, lane, acc);
        if (more) stash((c + 1) & 1);
        __syncthreads();
    }

    float* T = sm;
    frags_to_T(T, TLD, mW, nW, lane, acc);
    __syncthreads();

    for (int idx = tid; idx < 128 * 64; idx += 256) {
        int row = idx & 127, col = idx >> 7;
        C[(ll)b * cbat + (ll)(n0 + col) * ldc + m0 + row] = T[row * TLD + col];
    }
}

// ---------------- softmax: fp32 corr in -> fp16 pair planes out ----------------
__device__ __forceinline__ float wmaxf(float v) {
#pragma unroll
    for (int o = 16; o > 0; o >>= 1) v = fmaxf(v, __shfl_xor_sync(0xffffffffu, v, o));
    return v;
}
__device__ __forceinline__ float wsumf(float v) {
#pragma unroll
    for (int o = 16; o > 0; o >>= 1) v += __shfl_xor_sync(0xffffffffu, v, o);
    return v;
}
__global__ __launch_bounds__(256)
void smax_k(const float* __restrict__ S, __half* __restrict__ oh, __half* __restrict__ ol) {
    const ll row = blockIdx.x;
    const float4* p = reinterpret_cast<const float4*>(S + row * (ll)HWP);
    const int tid = threadIdx.x;
    const int lane = tid & 31, wid = tid >> 5;
    float4 v[4]; float mx = -3.0e38f;
#pragma unroll
    for (int i = 0; i < 4; i++) {
        v[i] = p[tid + 256 * i];
        mx = fmaxf(mx, fmaxf(fmaxf(v[i].x, v[i].y), fmaxf(v[i].z, v[i].w)));
    }
    __shared__ float red[8];
    mx = wmaxf(mx);
    if (lane == 0) red[wid] = mx;
    __syncthreads();
    if (wid == 0) { float t = (lane < 8) ? red[lane] : -3.0e38f; t = wmaxf(t); if (lane == 0) red[0] = t; }
    __syncthreads();
    mx = red[0];
    __syncthreads();
    float s = 0.f;
#pragma unroll
    for (int i = 0; i < 4; i++) {
        v[i].x = __expf(v[i].x - mx); v[i].y = __expf(v[i].y - mx);
        v[i].z = __expf(v[i].z - mx); v[i].w = __expf(v[i].w - mx);
        s += v[i].x + v[i].y + v[i].z + v[i].w;
    }
    s = wsumf(s);
    if (lane == 0) red[wid] = s;
    __syncthreads();
    if (wid == 0) { float t = (lane < 8) ? red[lane] : 0.f; t = wsumf(t); if (lane == 0) red[0] = t; }
    __syncthreads();
    const float inv = 1.f / red[0];
#pragma unroll
    for (int i = 0; i < 4; i++) {
        float a = v[i].x * inv, b2 = v[i].y * inv, c = v[i].z * inv, d = v[i].w * inv;
        __half ha, la, hb, lb, hc, lc, hd, ld2;
        h16(a, ha, la); h16(b2, hb, lb); h16(c, hc, lc); h16(d, hd, ld2);
        ll o = row * HWP + (ll)(tid + 256 * i) * 4;
        *reinterpret_cast<__half2*>(oh + o)     = __halves2half2(ha, hb);
        *reinterpret_cast<__half2*>(oh + o + 2) = __halves2half2(hc, hd);
        *reinterpret_cast<__half2*>(ol + o)     = __halves2half2(la, lb);
        *reinterpret_cast<__half2*>(ol + o + 2) = __halves2half2(lc, ld2);
    }
}

// ---------------- 2x2x2x2 mean pool on fp16 pairs ----------------
__global__ __launch_bounds__(256)
void poolp_k(const __half* __restrict__ ih, const __half* __restrict__ il,
             __half* __restrict__ oh, __half* __restrict__ ol, int g) {
    const int g2 = g >> 1;
    const int G2 = g2 * g2;
    const int halfP = G2 >> 1;
    const ll total = (ll)BB * G2 * halfP;
    ll idx = (ll)blockIdx.x * 256 + threadIdx.x;
    if (idx >= total) return;
    int t  = (int)(idx % halfP);
    int qp = (int)((idx / halfP) % G2);
    int b  = (int)(idx / ((ll)halfP * G2));
    const int Rh  = (2 * t) / g2;
    const int Rw0 = (2 * t) % g2;
    const int Qh = qp / g2, Qw = qp % g2;
    const ll G = (ll)g * g;
    const ll ibase = (ll)b * G * G;
    float s0 = 0.f, s1 = 0.f;
#pragma unroll
    for (int i = 0; i < 2; i++)
#pragma unroll
        for (int j = 0; j < 2; j++) {
            ll qrow = ibase + (ll)((2 * Qh + i) * g + 2 * Qw + j) * G;
#pragma unroll
            for (int u = 0; u < 2; u++) {
                ll wo = qrow + (ll)(2 * Rh + u) * g + 2 * Rw0;
                float2 a0 = __half22float2(*reinterpret_cast<const __half2*>(ih + wo));
                float2 b0 = __half22float2(*reinterpret_cast<const __half2*>(il + wo));
                float2 a1 = __half22float2(*reinterpret_cast<const __half2*>(ih + wo + 2));
                float2 b1 = __half22float2(*reinterpret_cast<const __half2*>(il + wo + 2));
                s0 += a0.x + b0.x + a0.y + b0.y;
                s1 += a1.x + b1.x + a1.y + b1.y;
            }
        }
    ll ob = ((ll)b * G2 + qp) * (ll)G2 + 2 * t;
    __half h, l;
    h16(s0 * (1.f / 16.f), h, l); oh[ob] = h; ol[ob] = l;
    h16(s1 * (1.f / 16.f), h, l); oh[ob + 1] = h; ol[ob + 1] = l;
}

// ---------------- host ----------------
#define GS(p, s) cudaGetSymbolAddress((void**)&p, s)

extern "C" void kernel_launch(void* const* d_in, const int* in_sizes, int n_in,
                              void* d_out, int out_size)
{
    const float* fd1 = (const float*)d_in[0];
    const float* fd2 = (const float*)d_in[1];
    const float* ref = (const float*)d_in[2];
    const float* o1  = (const float*)d_in[3];
    const float* o2  = (const float*)d_in[4];
    const float* tw1 = (const float*)d_in[5];
    const float* tb1 = (const float*)d_in[6];
    const float* tw2 = (const float*)d_in[7];
    const float* tb2 = (const float*)d_in[8];
    const float* pw1 = (const float*)d_in[9];
    const float* pb1 = (const float*)d_in[10];
    const float* pw2 = (const float*)d_in[11];
    const float* pb2 = (const float*)d_in[12];
    float* out = (float*)d_out;

    __half *x1h, *x1l, *x2h, *x2l, *th, *tl, *f1h, *f1l, *f2h, *f2l;
    __half *wbh, *wbl, *rfh, *rfl, *o1h, *o1l, *o2h, *o2l;
    __half *ch, *cl, *c1h, *c1l, *c2h, *c2l;
    float *corr;
    GS(x1h, g_x1h); GS(x1l, g_x1l); GS(x2h, g_x2h); GS(x2l, g_x2l);
    GS(th, g_th); GS(tl, g_tl);
    GS(f1h, g_f1h); GS(f1l, g_f1l); GS(f2h, g_f2h); GS(f2l, g_f2l);
    GS(wbh, g_wallh); GS(wbl, g_walll);
    GS(rfh, g_rfh); GS(rfl, g_rfl);
    GS(o1h, g_o1h); GS(o1l, g_o1l); GS(o2h, g_o2h); GS(o2l, g_o2l);
    GS(corr, g_corr); GS(ch, g_ch); GS(cl, g_cl);
    GS(c1h, g_c1h); GS(c1l, g_c1l); GS(c2h, g_c2h); GS(c2l, g_c2l);

    const size_t WSTR = (size_t)CC * KIMP;
    __half* w0h = wbh;            __half* w0l = wbl;
    __half* w1h = wbh + WSTR;     __half* w1l = wbl + WSTR;
    __half* w2h = wbh + 2 * WSTR; __half* w2l = wbl + 2 * WSTR;
    __half* w3h = wbh + 3 * WSTR; __half* w3l = wbl + 3 * WSTR;

    const int SMEM = 61440;
    cudaFuncSetAttribute(gc<1>, cudaFuncAttributeMaxDynamicSharedMemorySize, SMEM);
    cudaFuncSetAttribute(gc<2>, cudaFuncAttributeMaxDynamicSharedMemorySize, SMEM);
    cudaFuncSetAttribute(gx,    cudaFuncAttributeMaxDynamicSharedMemorySize, SMEM);
    cudaFuncSetAttribute(ga,    cudaFuncAttributeMaxDynamicSharedMemorySize, SMEM);

    const ll featB = (ll)HWP * CC;
    const ll refB  = (ll)CC * HWP;
    const int wGrid = (CC * KIMP + 255) / 256;
    const dim3 convG(32, 3, BB);

    // prep (3 launches — keeps launch #6 = gc<1> for ncu capture window)
    {
        dim3 g(HWP / 32, CC / 32, BB), blk(32, 8);
        tsplit_k<<<g, blk>>>(fd1, x1h, x1l);
        tsplit_k<<<g, blk>>>(fd2, x2h, x2l);
    }
    wsplit4_k<<<dim3(wGrid, 4), 256>>>(tw1, tw2, pw1, pw2, wbh, wbl);

    // theta resblock
    gc<1><<<convG, 256, SMEM>>>(w0h, w0l, x1h, x1l, featB, tb1, nullptr, 0, th, tl, featB);
    gc<2><<<convG, 256, SMEM>>>(w1h, w1l, th, tl, featB, tb2, fd1, refB, f1h, f1l, featB);
    // phi resblock
    gc<1><<<convG, 256, SMEM>>>(w2h, w2l, x2h, x2l, featB, pb1, nullptr, 0, th, tl, featB);
    gc<2><<<convG, 256, SMEM>>>(w3h, w3l, th, tl, featB, pb2, fd2, refB, f2h, f2l, featB);

    // ref / o1 / o2 splits (after convs; before ga)
    psplit_k<<<(int)(BB * refB / 4 + 255) / 256, 256>>>(ref, rfh, rfl, (int)(BB * refB));
    psplit_k<<<(BB * CC * 1024 / 4 + 255) / 256, 256>>>(o1, o1h, o1l, BB * CC * 1024);
    psplit_k<<<(BB * CC * 256 / 4 + 255) / 256, 256>>>(o2, o2h, o2l, BB * CC * 256);

    // corr = f1 f2^T, then softmax -> pair planes
    gx<<<dim3(32, 64, BB), 256, SMEM>>>(f1h, f1l, f2h, f2l, corr);
    smax_k<<<BB * HWP, 256>>>(corr, ch, cl);

    // out0: A=corr pairs [q][r], B=ref pairs [c][r] -> [c][q]
    ga<<<dim3(3, 32, BB), 256, SMEM>>>(ch, cl, (ll)HWP * HWP, HWP,
        rfh, rfl, refB, HWP, HWP, out, refB, HWP);

    // level 1
    {
        const ll total = (ll)BB * 1024 * 512;
        poolp_k<<<(int)((total + 255) / 256), 256>>>(ch, cl, c1h, c1l, 64);
        ga<<<dim3(3, 8, BB), 256, SMEM>>>(c1h, c1l, (ll)1024 * 1024, 1024,
            o1h, o1l, (ll)CC * 1024, 1024, 1024,
            out + (ll)BB * refB, (ll)CC * 1024, 1024);
    }
    // level 2
    {
        const ll total = (ll)BB * 256 * 128;
        poolp_k<<<(int)((total + 255) / 256), 256>>>(c1h, c1l, c2h, c2l, 32);
        ga<<<dim3(3, 2, BB), 256, SMEM>>>(c2h, c2l, (ll)256 * 256, 256,
            o2h, o2l, (ll)CC * 256, 256, 256,
            out + (ll)BB * refB + (ll)BB * CC * 1024, (ll)CC * 256, 256);
    }

    (void)in_sizes; (void)n_in; (void)out_size;
}